// round 16
// baseline (speedup 1.0000x reference)
#include <cuda_runtime.h>
#include <cuda_bf16.h>
#include <cstdint>

// Problem constants
#define Bq   2
#define Sq   2048
#define Dq   768
#define Hq   12
#define HDq  64
#define Mrows (Bq * Sq)   // 4096
#define K2   1536         // split bf16 K: [hi(768) | lo(768)]
#define BH   (Bq * Hq)    // 24

// ---------------- scratch (device globals: allocation-free) ----------------
__device__ float g_Q[Mrows * Dq];
__device__ float g_V[Mrows * Dq];
__device__ __nv_bfloat16 g_Isp[3][Mrows * K2];  // split query/key_/value
__device__ __nv_bfloat16 g_Asp[Mrows * K2];     // split attention output
__device__ __nv_bfloat16 g_Wsp[4][Dq * K2];     // split+transposed Wq,Wk,Wv,Wo
// Pre-split attention operands (per (b,h) plane)
__device__ __nv_bfloat16 g_KspH[BH * Sq * HDq]; // K hi  [bh][s][d]
__device__ __nv_bfloat16 g_KspL[BH * Sq * HDq]; // K lo
__device__ __nv_bfloat16 g_VtH[BH * HDq * Sq];  // V^T hi [bh][d][s]
__device__ __nv_bfloat16 g_VtL[BH * HDq * Sq];  // V^T lo

__device__ __forceinline__ float ex2f(float x) {
    float y;
    asm("ex2.approx.ftz.f32 %0, %1;" : "=f"(y) : "f"(x));
    return y;
}
__device__ __forceinline__ uint32_t smem_u32(const void* p) {
    uint32_t a;
    asm("{ .reg .u64 t; cvta.to.shared.u64 t, %1; cvt.u32.u64 %0, t; }"
        : "=r"(a) : "l"(p));
    return a;
}
__device__ __forceinline__ uint32_t packbf(float x, float y) {
    __nv_bfloat162 t = __floats2bfloat162_rn(x, y);   // .x = low half
    return *(uint32_t*)&t;
}
__device__ __forceinline__ float2 unpackbf(uint32_t u) {
    __nv_bfloat162 t = *(__nv_bfloat162*)&u;
    return __bfloat1622float2(t);
}

// ---- compute_80-baseline tensor ops (compile under compute_103) -----------
__device__ __forceinline__ void mma16816(float* c, const uint32_t* a,
                                         uint32_t b0, uint32_t b1) {
    asm volatile(
        "mma.sync.aligned.m16n8k16.row.col.f32.bf16.bf16.f32 "
        "{%0,%1,%2,%3}, {%4,%5,%6,%7}, {%8,%9}, {%0,%1,%2,%3};"
        : "+f"(c[0]), "+f"(c[1]), "+f"(c[2]), "+f"(c[3])
        : "r"(a[0]), "r"(a[1]), "r"(a[2]), "r"(a[3]), "r"(b0), "r"(b1));
}
__device__ __forceinline__ void ldsm4(uint32_t* r, uint32_t addr) {
    asm volatile("ldmatrix.sync.aligned.m8n8.x4.shared.b16 {%0,%1,%2,%3}, [%4];"
        : "=r"(r[0]), "=r"(r[1]), "=r"(r[2]), "=r"(r[3]) : "r"(addr));
}
__device__ __forceinline__ void ldsm2(uint32_t* r, uint32_t addr) {
    asm volatile("ldmatrix.sync.aligned.m8n8.x2.shared.b16 {%0,%1}, [%2];"
        : "=r"(r[0]), "=r"(r[1]) : "r"(addr));
}
__device__ __forceinline__ void cpasync16(uint32_t saddr, const void* g) {
    asm volatile("cp.async.cg.shared.global [%0], [%1], 16;"
                 :: "r"(saddr), "l"(g) : "memory");
}
#define CP_COMMIT() asm volatile("cp.async.commit_group;" ::: "memory")
#define CP_WAIT(n)  asm volatile("cp.async.wait_group %0;" :: "n"(n) : "memory")

// ---------------------------------------------------------------------------
// Split kernels: fp32 -> [bf16 hi | bf16 lo]  (row-major, K2 = 1536 cols)
// ---------------------------------------------------------------------------
struct SplitInArgs { const float* src[3]; __nv_bfloat16* dst[3]; };

__global__ void split_in_kernel(SplitInArgs a) {
    const float4* src = (const float4*)a.src[blockIdx.z];
    __nv_bfloat16* dst = a.dst[blockIdx.z];
    int idx = blockIdx.x * 256 + threadIdx.x;           // f4 idx, 786432 total
    float4 v = src[idx];
    int r = idx / 192, c = (idx % 192) * 4;
    __nv_bfloat16 h0 = __float2bfloat16(v.x), h1 = __float2bfloat16(v.y);
    __nv_bfloat16 h2 = __float2bfloat16(v.z), h3 = __float2bfloat16(v.w);
    __nv_bfloat16 l0 = __float2bfloat16(v.x - __bfloat162float(h0));
    __nv_bfloat16 l1 = __float2bfloat16(v.y - __bfloat162float(h1));
    __nv_bfloat16 l2 = __float2bfloat16(v.z - __bfloat162float(h2));
    __nv_bfloat16 l3 = __float2bfloat16(v.w - __bfloat162float(h3));
    __nv_bfloat162* dh = (__nv_bfloat162*)&dst[(size_t)r * K2 + c];
    dh[0] = __halves2bfloat162(h0, h1);
    dh[1] = __halves2bfloat162(h2, h3);
    __nv_bfloat162* dl = (__nv_bfloat162*)&dst[(size_t)r * K2 + 768 + c];
    dl[0] = __halves2bfloat162(l0, l1);
    dl[1] = __halves2bfloat162(l2, l3);
}

struct SplitWArgs { const float* W[4]; __nv_bfloat16* Wt[4]; };

// W[k][n] -> Wt[n][hi(768)|lo(768)] via 32x32 smem tile transpose.
__global__ void split_w_kernel(SplitWArgs a) {
    __shared__ float t[32][33];
    const float* W = a.W[blockIdx.z];
    __nv_bfloat16* Wt = a.Wt[blockIdx.z];
    int k0 = blockIdx.x * 32, n0 = blockIdx.y * 32;
    int x = threadIdx.x, y0 = threadIdx.y;          // block (32, 8)
#pragma unroll
    for (int j = y0; j < 32; j += 8)
        t[j][x] = W[(size_t)(k0 + j) * Dq + n0 + x];
    __syncthreads();
#pragma unroll
    for (int j = y0; j < 32; j += 8) {
        float v = t[x][j];
        __nv_bfloat16 h = __float2bfloat16(v);
        __nv_bfloat16 l = __float2bfloat16(v - __bfloat162float(h));
        Wt[(size_t)(n0 + j) * K2 + k0 + x] = h;
        Wt[(size_t)(n0 + j) * K2 + 768 + k0 + x] = l;
    }
}

// V fp32 [b][s][D] (head slice) -> transposed split bf16 [bh][d][s]
__global__ void transpose_v_kernel(const float* __restrict__ Vf,
                                   __nv_bfloat16* __restrict__ H,
                                   __nv_bfloat16* __restrict__ L) {
    __shared__ float t[32][33];
    int bh = blockIdx.z, b = bh / Hq, h = bh % Hq;
    int s0 = blockIdx.x * 32, d0 = blockIdx.y * 32;
    int x = threadIdx.x, y0 = threadIdx.y;          // block (32, 8)
#pragma unroll
    for (int j = y0; j < 32; j += 8)
        t[j][x] = Vf[(size_t)(b * Sq + s0 + j) * Dq + h * HDq + d0 + x];
    __syncthreads();
#pragma unroll
    for (int j = y0; j < 32; j += 8) {
        float v = t[x][j];                          // = V[s0+x][d0+j]
        __nv_bfloat16 hh = __float2bfloat16(v);
        __nv_bfloat16 ll = __float2bfloat16(v - __bfloat162float(hh));
        size_t off = (size_t)bh * HDq * Sq + (size_t)(d0 + j) * Sq + s0 + x;
        H[off] = hh;
        L[off] = ll;
    }
}

// ---------------------------------------------------------------------------
// HMMA GEMM, templated on NB (cols per warp / 8): BN = 32*NB CTA tile width.
// NB=4 -> 128 cols (QKV), NB=3 -> 96 cols (O-proj: 256 CTAs = 86% wave fill
// vs 65% at 128). kmode[z]=1: epilogue writes split-bf16 K planes directly
// (replaces the split_k kernel; identical rn splits of the same fp32 value).
// Double-buffered, single-sync, 2 CTAs/SM (R12 pipeline).
// ---------------------------------------------------------------------------
struct TcGemmArgs {
    const __nv_bfloat16* A[3];
    const __nv_bfloat16* Wt[3];
    const float* bias[3];
    float* C[3];
    int kmode[3];
    __nv_bfloat16* KH[3];
    __nv_bfloat16* KL[3];
};

#define PITCH 80
#define ABUF  (128 * PITCH)

template<int NB>
__global__ __launch_bounds__(256, 2) void gemm_tc_kernel(TcGemmArgs args)
{
    constexpr int BN = 32 * NB;
    constexpr int BUFSZ = (128 + BN) * PITCH;
    __shared__ __align__(16) char sbuf[2 * BUFSZ];
    const uint32_t sbase = smem_u32(sbuf);

    const int z = blockIdx.z;
    const __nv_bfloat16* __restrict__ A  = args.A[z];
    const __nv_bfloat16* __restrict__ Wt = args.Wt[z];
    const int tid = threadIdx.x, wid = tid >> 5, lane = tid & 31;
    const int wm = wid & 1, wn = wid >> 1;
    const int m0 = blockIdx.x * 128, n0 = blockIdx.y * BN;

    float acc[4][NB][4];
#pragma unroll
    for (int mt = 0; mt < 4; mt++)
#pragma unroll
        for (int nt = 0; nt < NB; nt++)
#pragma unroll
            for (int i = 0; i < 4; i++) acc[mt][nt][i] = 0.f;

    const int r_ld = tid >> 2, kq = tid & 3;

    auto load_chunk = [&](int it, int buf) {
        const int seg = it / 24, c = it % 24;
        const int aoff = ((seg == 1) ? 768 : 0) + c * 32;
        const int boff = ((seg == 2) ? 768 : 0) + c * 32;
        uint32_t sA = sbase + buf * BUFSZ;
        uint32_t sB = sA + 128 * PITCH;
#pragma unroll
        for (int i = 0; i < 2; i++) {
            int r = r_ld + 64 * i;
            cpasync16(sA + r * PITCH + kq * 16,
                      &A[(size_t)(m0 + r) * K2 + aoff + kq * 8]);
            if (r < BN)
                cpasync16(sB + r * PITCH + kq * 16,
                          &Wt[(size_t)(n0 + r) * K2 + boff + kq * 8]);
        }
    };

    load_chunk(0, 0);
    CP_COMMIT();

    const uint32_t a_off = (uint32_t)((wm * 64 + (lane & 15)) * PITCH +
                                      ((lane >> 4) << 4));
    const uint32_t b_off = (uint32_t)((wn * NB * 8 + (lane & 7) +
                                       ((lane >> 4) << 3)) * PITCH +
                                      (((lane >> 3) & 1) << 4));
    // odd-tail (8-row) fragment base for NB odd
    const uint32_t bodd_off = (uint32_t)((wn * NB * 8 + (NB & ~1) * 8 +
                                          (lane & 7)) * PITCH +
                                         (((lane >> 3) & 1) << 4));

    for (int it = 0; it < 72; it++) {
        const int buf = it & 1;
        CP_WAIT(0);                        // load(it) complete
        __syncthreads();                   // all compute(it-1) on buf^1 done
        if (it + 1 < 72) { load_chunk(it + 1, buf ^ 1); CP_COMMIT(); }

        uint32_t sA = sbase + buf * BUFSZ;
        uint32_t sB = sA + 128 * PITCH;
#pragma unroll
        for (int k16 = 0; k16 < 2; k16++) {
            uint32_t af[4][4], bf[(NB + 1) / 2][4];
#pragma unroll
            for (int mt = 0; mt < 4; mt++)
                ldsm4(af[mt], sA + a_off + mt * 16 * PITCH + k16 * 32);
#pragma unroll
            for (int pr = 0; pr < NB / 2; pr++)
                ldsm4(bf[pr], sB + b_off + pr * 16 * PITCH + k16 * 32);
            if (NB & 1)
                ldsm2(bf[NB / 2], sB + bodd_off + k16 * 32);
#pragma unroll
            for (int mt = 0; mt < 4; mt++)
#pragma unroll
                for (int nt = 0; nt < NB; nt++)
                    mma16816(acc[mt][nt], af[mt],
                             bf[nt >> 1][2 * (nt & 1)],
                             bf[nt >> 1][2 * (nt & 1) + 1]);
        }
    }

    const float* __restrict__ bias = args.bias[z];
    const int g = lane >> 2, tc = (lane & 3) * 2;
    if (!args.kmode[z]) {
        float* __restrict__ C = args.C[z];
#pragma unroll
        for (int mt = 0; mt < 4; mt++) {
            int row0 = m0 + wm * 64 + mt * 16 + g;
#pragma unroll
            for (int nt = 0; nt < NB; nt++) {
                int col = n0 + wn * NB * 8 + nt * 8 + tc;
                float b0 = bias[col], b1 = bias[col + 1];
                float2 v0 = make_float2(acc[mt][nt][0] + b0, acc[mt][nt][1] + b1);
                float2 v1 = make_float2(acc[mt][nt][2] + b0, acc[mt][nt][3] + b1);
                *(float2*)&C[(size_t)row0 * Dq + col] = v0;
                *(float2*)&C[(size_t)(row0 + 8) * Dq + col] = v1;
            }
        }
    } else {
        // Write split-bf16 K planes [bh][s][64] directly (replaces split_k)
        __nv_bfloat16* __restrict__ KH = args.KH[z];
        __nv_bfloat16* __restrict__ KL = args.KL[z];
#pragma unroll
        for (int mt = 0; mt < 4; mt++) {
            int row0 = m0 + wm * 64 + mt * 16 + g;
#pragma unroll
            for (int nt = 0; nt < NB; nt++) {
                int col = n0 + wn * NB * 8 + nt * 8 + tc;
                float b0 = bias[col], b1 = bias[col + 1];
#pragma unroll
                for (int rr = 0; rr < 2; rr++) {
                    int row = row0 + rr * 8;
                    float v0 = acc[mt][nt][2 * rr] + b0;
                    float v1 = acc[mt][nt][2 * rr + 1] + b1;
                    uint32_t hi = packbf(v0, v1);
                    float2 f = unpackbf(hi);
                    uint32_t lo = packbf(v0 - f.x, v1 - f.y);
                    int bh = (row >> 11) * Hq + (col >> 6);
                    size_t off = ((size_t)bh * Sq + (row & (Sq - 1))) * HDq +
                                 (col & 63);
                    *(uint32_t*)&KH[off] = hi;
                    *(uint32_t*)&KL[off] = lo;
                }
            }
        }
    }
}

// ---------------------------------------------------------------------------
// HMMA flash attention (R12 = 488us config): 128-key tiles, 1 CTA/SM,
// pre-split K/V, double-buffered, single-sync pipeline.
// Grid (S/128, H, B), 256 threads = 8 warps; warp w owns q rows w*16..+15.
// ---------------------------------------------------------------------------
#define QPB 72     // halves per Q/K smem row (144 B = 9x16B, odd -> ldsm-safe)
#define VPB 136    // halves per Vt smem row (272 B = 17x16B)
#define BUF_HALVES (18432 + 17408)
#define ATTN3_SMEM ((18432 + 2 * BUF_HALVES) * 2)   // 180224 B

__global__ __launch_bounds__(256, 1) void attn_tc_kernel(
    const float* __restrict__ Qg,
    const __nv_bfloat16* __restrict__ KspH, const __nv_bfloat16* __restrict__ KspL,
    const __nv_bfloat16* __restrict__ VtH,  const __nv_bfloat16* __restrict__ VtL,
    __nv_bfloat16* __restrict__ Osp)
{
    extern __shared__ __align__(16) char dsm[];
    __nv_bfloat16* const QH = (__nv_bfloat16*)dsm;
    __nv_bfloat16* const QL = QH + 128 * QPB;
    const uint32_t uQH = smem_u32(QH), uQL = smem_u32(QL);
    const uint32_t uBUF0 = uQH + 18432 * 2;          // byte addr of buffer 0

    const int tid = threadIdx.x, lane = tid & 31, wid = tid >> 5;
    const int g = lane >> 2, t = lane & 3;
    const int q0 = blockIdx.x * 128;
    const int h = blockIdx.y, b = blockIdx.z;
    const int bh = b * Hq + h;
    const size_t base = (size_t)b * Sq * Dq + (size_t)h * HDq;
    const __nv_bfloat16* kH = KspH + (size_t)bh * Sq * HDq;
    const __nv_bfloat16* kL = KspL + (size_t)bh * Sq * HDq;
    const __nv_bfloat16* vH = VtH + (size_t)bh * HDq * Sq;
    const __nv_bfloat16* vL = VtL + (size_t)bh * HDq * Sq;

    const float scl2 = 0.125f * 1.4426950408889634f;

    auto loadKV = [&](int kt, int buf) {
        const int k0 = kt * 128;
        const uint32_t ub = uBUF0 + buf * (BUF_HALVES * 2);
        const uint32_t uKH = ub, uKL = ub + 18432;
        const uint32_t uVH = ub + 36864, uVL = ub + 36864 + 17408;
#pragma unroll
        for (int i = 0; i < 4; i++) {
            int id = tid + 256 * i;
            int r = id >> 3, c = id & 7;
            cpasync16(uKH + r * 144 + c * 16, &kH[(size_t)(k0 + r) * HDq + c * 8]);
            cpasync16(uKL + r * 144 + c * 16, &kL[(size_t)(k0 + r) * HDq + c * 8]);
        }
#pragma unroll
        for (int i = 0; i < 4; i++) {
            int id = tid + 256 * i;
            int r = id >> 4, c = id & 15;
            cpasync16(uVH + r * 272 + c * 16, &vH[(size_t)r * Sq + k0 + c * 8]);
            cpasync16(uVL + r * 272 + c * 16, &vL[(size_t)r * Sq + k0 + c * 8]);
        }
    };

    loadKV(0, 0);
    CP_COMMIT();

    // Q tile -> scaled split bf16 (once per CTA; overlaps first K/V load)
#pragma unroll
    for (int i = 0; i < 8; i++) {
        int idx = tid + 256 * i;
        int r = idx >> 4, c = (idx & 15) << 2;
        float4 q = *(const float4*)&Qg[base + (size_t)(q0 + r) * Dq + c];
        q.x *= scl2; q.y *= scl2; q.z *= scl2; q.w *= scl2;
        uint32_t h01 = packbf(q.x, q.y), h23 = packbf(q.z, q.w);
        float2 f0 = unpackbf(h01), f1 = unpackbf(h23);
        *(uint32_t*)&QH[r * QPB + c]     = h01;
        *(uint32_t*)&QH[r * QPB + c + 2] = h23;
        *(uint32_t*)&QL[r * QPB + c]     = packbf(q.x - f0.x, q.y - f0.y);
        *(uint32_t*)&QL[r * QPB + c + 2] = packbf(q.z - f1.x, q.w - f1.y);
    }

    float m0 = -1e30f, m1 = -1e30f, l0 = 0.f, l1 = 0.f;
    float oacc[8][4];
#pragma unroll
    for (int nt = 0; nt < 8; nt++)
#pragma unroll
        for (int i = 0; i < 4; i++) oacc[nt][i] = 0.f;

    const uint32_t a_off  = (uint32_t)((wid * 16 + (lane & 15)) * 144 +
                                       ((lane >> 4) << 4));
    const uint32_t kb_off = (uint32_t)(((lane & 7) + ((lane >> 4) << 3)) * 144 +
                                       (((lane >> 3) & 1) << 4));
    const uint32_t vb_off = (uint32_t)(((lane & 7) + ((lane >> 4) << 3)) * 272 +
                                       (((lane >> 3) & 1) << 4));

    for (int kt = 0; kt < 16; kt++) {
        const int buf = kt & 1;
        CP_WAIT(0);                        // load(kt) complete
        __syncthreads();                   // all compute(kt-1) on buf^1 done
        if (kt + 1 < 16) { loadKV(kt + 1, buf ^ 1); CP_COMMIT(); }

        const uint32_t ub = uBUF0 + buf * (BUF_HALVES * 2);
        const uint32_t uKH = ub, uKL = ub + 18432;
        const uint32_t uVH = ub + 36864, uVL = ub + 36864 + 17408;

        // ---- QK^T: j-outer, Q frags loaded once per j ----
        float sacc[16][4];
#pragma unroll
        for (int nt = 0; nt < 16; nt++)
#pragma unroll
            for (int i = 0; i < 4; i++) sacc[nt][i] = 0.f;

#pragma unroll
        for (int j = 0; j < 4; j++) {
            uint32_t ah[4], al[4];
            ldsm4(ah, uQH + a_off + j * 32);
            ldsm4(al, uQL + a_off + j * 32);
#pragma unroll
            for (int p = 0; p < 8; p++) {
                uint32_t bh4[4], bl4[4];
                ldsm4(bh4, uKH + kb_off + p * (16 * 144) + j * 32);
                ldsm4(bl4, uKL + kb_off + p * (16 * 144) + j * 32);
                mma16816(sacc[2 * p],     ah, bh4[0], bh4[1]);
                mma16816(sacc[2 * p + 1], ah, bh4[2], bh4[3]);
                mma16816(sacc[2 * p],     al, bh4[0], bh4[1]);
                mma16816(sacc[2 * p + 1], al, bh4[2], bh4[3]);
                mma16816(sacc[2 * p],     ah, bl4[0], bl4[1]);
                mma16816(sacc[2 * p + 1], ah, bl4[2], bl4[3]);
            }
        }

        // ---- softmax (registers; rows owned by quads) ----
        float tmax0 = -1e30f, tmax1 = -1e30f;
#pragma unroll
        for (int nt = 0; nt < 16; nt++) {
            tmax0 = fmaxf(tmax0, fmaxf(sacc[nt][0], sacc[nt][1]));
            tmax1 = fmaxf(tmax1, fmaxf(sacc[nt][2], sacc[nt][3]));
        }
        tmax0 = fmaxf(tmax0, __shfl_xor_sync(0xffffffffu, tmax0, 1));
        tmax0 = fmaxf(tmax0, __shfl_xor_sync(0xffffffffu, tmax0, 2));
        tmax1 = fmaxf(tmax1, __shfl_xor_sync(0xffffffffu, tmax1, 1));
        tmax1 = fmaxf(tmax1, __shfl_xor_sync(0xffffffffu, tmax1, 2));
        float mn0 = fmaxf(m0, tmax0), mn1 = fmaxf(m1, tmax1);
        float al0 = ex2f(m0 - mn0),  al1 = ex2f(m1 - mn1);
        m0 = mn0; m1 = mn1;
        float s0 = 0.f, s1 = 0.f;
#pragma unroll
        for (int nt = 0; nt < 16; nt++) {
            sacc[nt][0] = ex2f(sacc[nt][0] - m0); s0 += sacc[nt][0];
            sacc[nt][1] = ex2f(sacc[nt][1] - m0); s0 += sacc[nt][1];
            sacc[nt][2] = ex2f(sacc[nt][2] - m1); s1 += sacc[nt][2];
            sacc[nt][3] = ex2f(sacc[nt][3] - m1); s1 += sacc[nt][3];
        }
        s0 += __shfl_xor_sync(0xffffffffu, s0, 1);
        s0 += __shfl_xor_sync(0xffffffffu, s0, 2);
        s1 += __shfl_xor_sync(0xffffffffu, s1, 1);
        s1 += __shfl_xor_sync(0xffffffffu, s1, 2);
        l0 = l0 * al0 + s0;
        l1 = l1 * al1 + s1;
#pragma unroll
        for (int nt = 0; nt < 8; nt++) {
            oacc[nt][0] *= al0; oacc[nt][1] *= al0;
            oacc[nt][2] *= al1; oacc[nt][3] *= al1;
        }

        // ---- PV: j-outer, P converted per-j (8 live P regs) ----
#pragma unroll
        for (int j = 0; j < 8; j++) {
            uint32_t Ph[4], Pl[4];
            {
                uint32_t u; float2 f;
                u = packbf(sacc[2*j][0], sacc[2*j][1]); Ph[0] = u;
                f = unpackbf(u);
                Pl[0] = packbf(sacc[2*j][0] - f.x, sacc[2*j][1] - f.y);
                u = packbf(sacc[2*j][2], sacc[2*j][3]); Ph[1] = u;
                f = unpackbf(u);
                Pl[1] = packbf(sacc[2*j][2] - f.x, sacc[2*j][3] - f.y);
                u = packbf(sacc[2*j+1][0], sacc[2*j+1][1]); Ph[2] = u;
                f = unpackbf(u);
                Pl[2] = packbf(sacc[2*j+1][0] - f.x, sacc[2*j+1][1] - f.y);
                u = packbf(sacc[2*j+1][2], sacc[2*j+1][3]); Ph[3] = u;
                f = unpackbf(u);
                Pl[3] = packbf(sacc[2*j+1][2] - f.x, sacc[2*j+1][3] - f.y);
            }
#pragma unroll
            for (int p = 0; p < 4; p++) {
                uint32_t vh4[4], vl4[4];
                ldsm4(vh4, uVH + vb_off + p * (16 * 272) + j * 32);
                ldsm4(vl4, uVL + vb_off + p * (16 * 272) + j * 32);
                mma16816(oacc[2 * p],     Ph, vh4[0], vh4[1]);
                mma16816(oacc[2 * p + 1], Ph, vh4[2], vh4[3]);
                mma16816(oacc[2 * p],     Pl, vh4[0], vh4[1]);
                mma16816(oacc[2 * p + 1], Pl, vh4[2], vh4[3]);
                mma16816(oacc[2 * p],     Ph, vl4[0], vl4[1]);
                mma16816(oacc[2 * p + 1], Ph, vl4[2], vl4[3]);
            }
        }
    }

    // ---- finalize: write split bf16 directly into O-proj input layout ----
    const int r0 = b * Sq + q0 + wid * 16 + g, r1 = r0 + 8;
    const float inv0 = 1.f / l0, inv1 = 1.f / l1;
#pragma unroll
    for (int nt = 0; nt < 8; nt++) {
        int col = h * 64 + nt * 8 + t * 2;
        float o00 = oacc[nt][0] * inv0, o01 = oacc[nt][1] * inv0;
        float o10 = oacc[nt][2] * inv1, o11 = oacc[nt][3] * inv1;
        uint32_t hi0 = packbf(o00, o01);
        float2 f0 = unpackbf(hi0);
        uint32_t lo0 = packbf(o00 - f0.x, o01 - f0.y);
        uint32_t hi1 = packbf(o10, o11);
        float2 f1 = unpackbf(hi1);
        uint32_t lo1 = packbf(o10 - f1.x, o11 - f1.y);
        *(uint32_t*)&Osp[(size_t)r0 * K2 + col]       = hi0;
        *(uint32_t*)&Osp[(size_t)r0 * K2 + 768 + col] = lo0;
        *(uint32_t*)&Osp[(size_t)r1 * K2 + col]       = hi1;
        *(uint32_t*)&Osp[(size_t)r1 * K2 + 768 + col] = lo1;
    }
}

// ---------------------------------------------------------------------------
extern "C" void kernel_launch(void* const* d_in, const int* in_sizes, int n_in,
                              void* d_out, int out_size)
{
    const float* query = (const float*)d_in[0];
    const float* key_  = (const float*)d_in[1];
    const float* value = (const float*)d_in[2];
    const float* Wq = (const float*)d_in[3];
    const float* bq = (const float*)d_in[4];
    const float* Wk = (const float*)d_in[5];
    const float* bk = (const float*)d_in[6];
    const float* Wv = (const float*)d_in[7];
    const float* bv = (const float*)d_in[8];
    const float* Wo = (const float*)d_in[9];
    const float* bo = (const float*)d_in[10];
    float* out = (float*)d_out;

    float *pQ, *pV;
    __nv_bfloat16 *pIsp, *pAsp, *pWsp, *pKH, *pKL, *pVH, *pVL;
    cudaGetSymbolAddress((void**)&pQ, g_Q);
    cudaGetSymbolAddress((void**)&pV, g_V);
    cudaGetSymbolAddress((void**)&pIsp, g_Isp);
    cudaGetSymbolAddress((void**)&pAsp, g_Asp);
    cudaGetSymbolAddress((void**)&pWsp, g_Wsp);
    cudaGetSymbolAddress((void**)&pKH, g_KspH);
    cudaGetSymbolAddress((void**)&pKL, g_KspL);
    cudaGetSymbolAddress((void**)&pVH, g_VtH);
    cudaGetSymbolAddress((void**)&pVL, g_VtL);

    cudaFuncSetAttribute(attn_tc_kernel,
                         cudaFuncAttributeMaxDynamicSharedMemorySize,
                         ATTN3_SMEM);

    // 1) split inputs -> bf16 hi|lo
    SplitInArgs si;
    si.src[0] = query; si.src[1] = key_; si.src[2] = value;
    si.dst[0] = pIsp;  si.dst[1] = pIsp + (size_t)Mrows * K2;
    si.dst[2] = pIsp + 2 * (size_t)Mrows * K2;
    split_in_kernel<<<dim3(3072, 1, 3), 256>>>(si);

    // 2) split + transpose weights
    SplitWArgs sw;
    sw.W[0] = Wq; sw.W[1] = Wk; sw.W[2] = Wv; sw.W[3] = Wo;
    for (int i = 0; i < 4; i++) sw.Wt[i] = pWsp + (size_t)i * Dq * K2;
    split_w_kernel<<<dim3(24, 24, 4), dim3(32, 8)>>>(sw);

    // 3) QKV projections; K (z=1) writes split planes directly (kmode)
    TcGemmArgs qkv = {};
    for (int i = 0; i < 3; i++) {
        qkv.A[i]  = pIsp + (size_t)i * Mrows * K2;
        qkv.Wt[i] = pWsp + (size_t)i * Dq * K2;
    }
    qkv.bias[0] = bq; qkv.bias[1] = bk; qkv.bias[2] = bv;
    qkv.C[0] = pQ;    qkv.C[1] = pQ;    qkv.C[2] = pV;   // C[1] unused
    qkv.kmode[0] = 0; qkv.kmode[1] = 1; qkv.kmode[2] = 0;
    qkv.KH[1] = pKH;  qkv.KL[1] = pKL;
    gemm_tc_kernel<4><<<dim3(Mrows / 128, Dq / 128, 3), 256>>>(qkv);

    // 4) transpose-split V (K split now fused into the GEMM epilogue)
    transpose_v_kernel<<<dim3(Sq / 32, HDq / 32, BH), dim3(32, 8)>>>(pV, pVH, pVL);

    // 5) attention (HMMA R12 config)
    dim3 ga(Sq / 128, Hq, Bq);
    attn_tc_kernel<<<ga, 256, ATTN3_SMEM>>>(pQ, pKH, pKL, pVH, pVL, pAsp);

    // 6) output projection: 96-col tiles -> 256 CTAs = 86% single-wave fill
    TcGemmArgs og = {};
    og.A[0] = pAsp; og.Wt[0] = pWsp + 3 * (size_t)Dq * K2;
    og.bias[0] = bo; og.C[0] = out;
    og.A[1] = og.A[2] = pAsp; og.Wt[1] = og.Wt[2] = og.Wt[0];
    og.bias[1] = og.bias[2] = bo; og.C[1] = og.C[2] = og.C[0];
    gemm_tc_kernel<3><<<dim3(Mrows / 128, Dq / 96, 1), 256>>>(og);
}

// round 17
// speedup vs baseline: 1.5120x; 1.5120x over previous
#include <cuda_runtime.h>
#include <cuda_bf16.h>
#include <cstdint>

// Problem constants
#define Bq   2
#define Sq   2048
#define Dq   768
#define Hq   12
#define HDq  64
#define Mrows (Bq * Sq)   // 4096
#define K2   1536         // split bf16 K: [hi(768) | lo(768)]
#define BH   (Bq * Hq)    // 24

// ---------------- scratch (device globals: allocation-free) ----------------
__device__ float g_Q[Mrows * Dq];
__device__ float g_K[Mrows * Dq];
__device__ float g_V[Mrows * Dq];
__device__ __nv_bfloat16 g_Isp[3][Mrows * K2];  // split query/key_/value
__device__ __nv_bfloat16 g_Asp[Mrows * K2];     // split attention output
__device__ __nv_bfloat16 g_Wsp[4][Dq * K2];     // split+transposed Wq,Wk,Wv,Wo
// Pre-split attention operands (per (b,h) plane)
__device__ __nv_bfloat16 g_KspH[BH * Sq * HDq]; // K hi  [bh][s][d]
__device__ __nv_bfloat16 g_KspL[BH * Sq * HDq]; // K lo
__device__ __nv_bfloat16 g_VtH[BH * HDq * Sq];  // V^T hi [bh][d][s]
__device__ __nv_bfloat16 g_VtL[BH * HDq * Sq];  // V^T lo

__device__ __forceinline__ float ex2f(float x) {
    float y;
    asm("ex2.approx.ftz.f32 %0, %1;" : "=f"(y) : "f"(x));
    return y;
}
__device__ __forceinline__ uint32_t smem_u32(const void* p) {
    uint32_t a;
    asm("{ .reg .u64 t; cvta.to.shared.u64 t, %1; cvt.u32.u64 %0, t; }"
        : "=r"(a) : "l"(p));
    return a;
}
__device__ __forceinline__ uint32_t packbf(float x, float y) {
    __nv_bfloat162 t = __floats2bfloat162_rn(x, y);   // .x = low half
    return *(uint32_t*)&t;
}
__device__ __forceinline__ float2 unpackbf(uint32_t u) {
    __nv_bfloat162 t = *(__nv_bfloat162*)&u;
    return __bfloat1622float2(t);
}

// ---- compute_80-baseline tensor ops (compile under compute_103) -----------
__device__ __forceinline__ void mma16816(float* c, const uint32_t* a,
                                         uint32_t b0, uint32_t b1) {
    asm volatile(
        "mma.sync.aligned.m16n8k16.row.col.f32.bf16.bf16.f32 "
        "{%0,%1,%2,%3}, {%4,%5,%6,%7}, {%8,%9}, {%0,%1,%2,%3};"
        : "+f"(c[0]), "+f"(c[1]), "+f"(c[2]), "+f"(c[3])
        : "r"(a[0]), "r"(a[1]), "r"(a[2]), "r"(a[3]), "r"(b0), "r"(b1));
}
__device__ __forceinline__ void ldsm4(uint32_t* r, uint32_t addr) {
    asm volatile("ldmatrix.sync.aligned.m8n8.x4.shared.b16 {%0,%1,%2,%3}, [%4];"
        : "=r"(r[0]), "=r"(r[1]), "=r"(r[2]), "=r"(r[3]) : "r"(addr));
}
__device__ __forceinline__ void ldsm2(uint32_t* r, uint32_t addr) {
    asm volatile("ldmatrix.sync.aligned.m8n8.x2.shared.b16 {%0,%1}, [%2];"
        : "=r"(r[0]), "=r"(r[1]) : "r"(addr));
}
__device__ __forceinline__ void cpasync16(uint32_t saddr, const void* g) {
    asm volatile("cp.async.cg.shared.global [%0], [%1], 16;"
                 :: "r"(saddr), "l"(g) : "memory");
}
#define CP_COMMIT() asm volatile("cp.async.commit_group;" ::: "memory")
#define CP_WAIT(n)  asm volatile("cp.async.wait_group %0;" :: "n"(n) : "memory")

// ---------------------------------------------------------------------------
// Split kernels: fp32 -> [bf16 hi | bf16 lo]  (row-major, K2 = 1536 cols)
// ---------------------------------------------------------------------------
struct SplitInArgs { const float* src[3]; __nv_bfloat16* dst[3]; };

__global__ void split_in_kernel(SplitInArgs a) {
    const float4* src = (const float4*)a.src[blockIdx.z];
    __nv_bfloat16* dst = a.dst[blockIdx.z];
    int idx = blockIdx.x * 256 + threadIdx.x;           // f4 idx, 786432 total
    float4 v = src[idx];
    int r = idx / 192, c = (idx % 192) * 4;
    __nv_bfloat16 h0 = __float2bfloat16(v.x), h1 = __float2bfloat16(v.y);
    __nv_bfloat16 h2 = __float2bfloat16(v.z), h3 = __float2bfloat16(v.w);
    __nv_bfloat16 l0 = __float2bfloat16(v.x - __bfloat162float(h0));
    __nv_bfloat16 l1 = __float2bfloat16(v.y - __bfloat162float(h1));
    __nv_bfloat16 l2 = __float2bfloat16(v.z - __bfloat162float(h2));
    __nv_bfloat16 l3 = __float2bfloat16(v.w - __bfloat162float(h3));
    __nv_bfloat162* dh = (__nv_bfloat162*)&dst[(size_t)r * K2 + c];
    dh[0] = __halves2bfloat162(h0, h1);
    dh[1] = __halves2bfloat162(h2, h3);
    __nv_bfloat162* dl = (__nv_bfloat162*)&dst[(size_t)r * K2 + 768 + c];
    dl[0] = __halves2bfloat162(l0, l1);
    dl[1] = __halves2bfloat162(l2, l3);
}

struct SplitWArgs { const float* W[4]; __nv_bfloat16* Wt[4]; };

// W[k][n] -> Wt[n][hi(768)|lo(768)] via 32x32 smem tile transpose.
__global__ void split_w_kernel(SplitWArgs a) {
    __shared__ float t[32][33];
    const float* W = a.W[blockIdx.z];
    __nv_bfloat16* Wt = a.Wt[blockIdx.z];
    int k0 = blockIdx.x * 32, n0 = blockIdx.y * 32;
    int x = threadIdx.x, y0 = threadIdx.y;          // block (32, 8)
#pragma unroll
    for (int j = y0; j < 32; j += 8)
        t[j][x] = W[(size_t)(k0 + j) * Dq + n0 + x];
    __syncthreads();
#pragma unroll
    for (int j = y0; j < 32; j += 8) {
        float v = t[x][j];
        __nv_bfloat16 h = __float2bfloat16(v);
        __nv_bfloat16 l = __float2bfloat16(v - __bfloat162float(h));
        Wt[(size_t)(n0 + j) * K2 + k0 + x] = h;
        Wt[(size_t)(n0 + j) * K2 + 768 + k0 + x] = l;
    }
}

// K fp32 [b][s][D] (head slice) -> per-plane split bf16 [bh][s][64]
__global__ void split_k_kernel(const float* __restrict__ Kf,
                               __nv_bfloat16* __restrict__ H,
                               __nv_bfloat16* __restrict__ L) {
    int idx = blockIdx.x * 256 + threadIdx.x;       // 786432 f4
    int bh = idx >> 15, rem = idx & 32767;
    int s = rem >> 4, d = (rem & 15) << 2;
    int b = bh / Hq, h = bh % Hq;
    float4 v = *(const float4*)&Kf[(size_t)(b * Sq + s) * Dq + h * HDq + d];
    size_t off = (size_t)bh * Sq * HDq + s * HDq + d;
    uint32_t h01 = packbf(v.x, v.y), h23 = packbf(v.z, v.w);
    float2 f0 = unpackbf(h01), f1 = unpackbf(h23);
    *(uint32_t*)&H[off]     = h01;
    *(uint32_t*)&H[off + 2] = h23;
    *(uint32_t*)&L[off]     = packbf(v.x - f0.x, v.y - f0.y);
    *(uint32_t*)&L[off + 2] = packbf(v.z - f1.x, v.w - f1.y);
}

// V fp32 [b][s][D] (head slice) -> transposed split bf16 [bh][d][s]
__global__ void transpose_v_kernel(const float* __restrict__ Vf,
                                   __nv_bfloat16* __restrict__ H,
                                   __nv_bfloat16* __restrict__ L) {
    __shared__ float t[32][33];
    int bh = blockIdx.z, b = bh / Hq, h = bh % Hq;
    int s0 = blockIdx.x * 32, d0 = blockIdx.y * 32;
    int x = threadIdx.x, y0 = threadIdx.y;          // block (32, 8)
#pragma unroll
    for (int j = y0; j < 32; j += 8)
        t[j][x] = Vf[(size_t)(b * Sq + s0 + j) * Dq + h * HDq + d0 + x];
    __syncthreads();
#pragma unroll
    for (int j = y0; j < 32; j += 8) {
        float v = t[x][j];                          // = V[s0+x][d0+j]
        __nv_bfloat16 hh = __float2bfloat16(v);
        __nv_bfloat16 ll = __float2bfloat16(v - __bfloat162float(hh));
        size_t off = (size_t)bh * HDq * Sq + (size_t)(d0 + j) * Sq + s0 + x;
        H[off] = hh;
        L[off] = ll;
    }
}

// ---------------------------------------------------------------------------
// HMMA GEMM (R12 config = 488us baseline, VERBATIM): 128x128 tile,
// double-buffered, single-sync, 2 CTAs/SM, static smem 40KB.
// ---------------------------------------------------------------------------
struct TcGemmArgs {
    const __nv_bfloat16* A[3];
    const __nv_bfloat16* Wt[3];
    const float* bias[3];
    float* C[3];
};

#define PITCH 80
#define ABUF  (128 * PITCH)

__global__ __launch_bounds__(256, 2) void gemm_tc_kernel(TcGemmArgs args)
{
    __shared__ __align__(16) char sbuf[4 * ABUF];
    const uint32_t sbase = smem_u32(sbuf);

    const int z = blockIdx.z;
    const __nv_bfloat16* __restrict__ A  = args.A[z];
    const __nv_bfloat16* __restrict__ Wt = args.Wt[z];
    const int tid = threadIdx.x, wid = tid >> 5, lane = tid & 31;
    const int wm = wid & 1, wn = wid >> 1;
    const int m0 = blockIdx.x * 128, n0 = blockIdx.y * 128;

    float acc[4][4][4];
#pragma unroll
    for (int mt = 0; mt < 4; mt++)
#pragma unroll
        for (int nt = 0; nt < 4; nt++)
#pragma unroll
            for (int i = 0; i < 4; i++) acc[mt][nt][i] = 0.f;

    const int r_ld = tid >> 2, kq = tid & 3;

    auto load_chunk = [&](int it, int buf) {
        const int seg = it / 24, c = it % 24;
        const int aoff = ((seg == 1) ? 768 : 0) + c * 32;
        const int boff = ((seg == 2) ? 768 : 0) + c * 32;
        uint32_t sA = sbase + buf * 2 * ABUF;
        uint32_t sB = sA + ABUF;
#pragma unroll
        for (int i = 0; i < 2; i++) {
            int r = r_ld + 64 * i;
            cpasync16(sA + r * PITCH + kq * 16,
                      &A[(size_t)(m0 + r) * K2 + aoff + kq * 8]);
            cpasync16(sB + r * PITCH + kq * 16,
                      &Wt[(size_t)(n0 + r) * K2 + boff + kq * 8]);
        }
    };

    load_chunk(0, 0);
    CP_COMMIT();

    const uint32_t a_off = (uint32_t)((wm * 64 + (lane & 15)) * PITCH +
                                      ((lane >> 4) << 4));
    const uint32_t b_off = (uint32_t)((wn * 32 + (lane & 7) +
                                       ((lane >> 4) << 3)) * PITCH +
                                      (((lane >> 3) & 1) << 4));

    for (int it = 0; it < 72; it++) {
        const int buf = it & 1;
        CP_WAIT(0);                        // load(it) complete
        __syncthreads();                   // all compute(it-1) on buf^1 done
        if (it + 1 < 72) { load_chunk(it + 1, buf ^ 1); CP_COMMIT(); }

        uint32_t sA = sbase + buf * 2 * ABUF;
        uint32_t sB = sA + ABUF;
#pragma unroll
        for (int k16 = 0; k16 < 2; k16++) {
            uint32_t af[4][4], bf[2][4];
#pragma unroll
            for (int mt = 0; mt < 4; mt++)
                ldsm4(af[mt], sA + a_off + mt * 16 * PITCH + k16 * 32);
#pragma unroll
            for (int pr = 0; pr < 2; pr++)
                ldsm4(bf[pr], sB + b_off + pr * 16 * PITCH + k16 * 32);
#pragma unroll
            for (int mt = 0; mt < 4; mt++)
#pragma unroll
                for (int pr = 0; pr < 2; pr++) {
                    mma16816(acc[mt][2 * pr],     af[mt], bf[pr][0], bf[pr][1]);
                    mma16816(acc[mt][2 * pr + 1], af[mt], bf[pr][2], bf[pr][3]);
                }
        }
    }

    const float* __restrict__ bias = args.bias[z];
    float* __restrict__ C = args.C[z];
    const int g = lane >> 2, tc = (lane & 3) * 2;
#pragma unroll
    for (int mt = 0; mt < 4; mt++) {
        int row0 = m0 + wm * 64 + mt * 16 + g;
#pragma unroll
        for (int nt = 0; nt < 4; nt++) {
            int col = n0 + wn * 32 + nt * 8 + tc;
            float b0 = bias[col], b1 = bias[col + 1];
            float2 v0 = make_float2(acc[mt][nt][0] + b0, acc[mt][nt][1] + b1);
            float2 v1 = make_float2(acc[mt][nt][2] + b0, acc[mt][nt][3] + b1);
            *(float2*)&C[(size_t)row0 * Dq + col] = v0;
            *(float2*)&C[(size_t)(row0 + 8) * Dq + col] = v1;
        }
    }
}

// ---------------------------------------------------------------------------
// O-projection GEMM: SEPARATE hardcoded 128x96 kernel (256 CTAs = 86% of one
// wave vs 65% at 128 cols). Single fp32 epilogue; NB=3 ldsm2 tail path was
// correctness-validated in R16. ~100 regs -> no spill under the 2-CTA cap.
// ---------------------------------------------------------------------------
#define BBUF96 (96 * PITCH)
#define BUFSZ96 (ABUF + BBUF96)          // 17920 B per stage

__global__ __launch_bounds__(256, 2) void gemm_tc96_kernel(
    const __nv_bfloat16* __restrict__ A,
    const __nv_bfloat16* __restrict__ Wt,
    const float* __restrict__ bias,
    float* __restrict__ C)
{
    __shared__ __align__(16) char sbuf[2 * BUFSZ96];
    const uint32_t sbase = smem_u32(sbuf);

    const int tid = threadIdx.x, wid = tid >> 5, lane = tid & 31;
    const int wm = wid & 1, wn = wid >> 1;           // 2(m) x 4(n), 24 cols/warp
    const int m0 = blockIdx.x * 128, n0 = blockIdx.y * 96;

    float acc[4][3][4];
#pragma unroll
    for (int mt = 0; mt < 4; mt++)
#pragma unroll
        for (int nt = 0; nt < 3; nt++)
#pragma unroll
            for (int i = 0; i < 4; i++) acc[mt][nt][i] = 0.f;

    const int r_ld = tid >> 2, kq = tid & 3;

    auto load_chunk = [&](int it, int buf) {
        const int seg = it / 24, c = it % 24;
        const int aoff = ((seg == 1) ? 768 : 0) + c * 32;
        const int boff = ((seg == 2) ? 768 : 0) + c * 32;
        uint32_t sA = sbase + buf * BUFSZ96;
        uint32_t sB = sA + ABUF;
#pragma unroll
        for (int i = 0; i < 2; i++) {
            int r = r_ld + 64 * i;
            cpasync16(sA + r * PITCH + kq * 16,
                      &A[(size_t)(m0 + r) * K2 + aoff + kq * 8]);
            if (r < 96)
                cpasync16(sB + r * PITCH + kq * 16,
                          &Wt[(size_t)(n0 + r) * K2 + boff + kq * 8]);
        }
    };

    load_chunk(0, 0);
    CP_COMMIT();

    const uint32_t a_off = (uint32_t)((wm * 64 + (lane & 15)) * PITCH +
                                      ((lane >> 4) << 4));
    const uint32_t b_off = (uint32_t)((wn * 24 + (lane & 7) +
                                       ((lane >> 4) << 3)) * PITCH +
                                      (((lane >> 3) & 1) << 4));
    const uint32_t bodd_off = (uint32_t)((wn * 24 + 16 + (lane & 7)) * PITCH +
                                         (((lane >> 3) & 1) << 4));

    for (int it = 0; it < 72; it++) {
        const int buf = it & 1;
        CP_WAIT(0);
        __syncthreads();
        if (it + 1 < 72) { load_chunk(it + 1, buf ^ 1); CP_COMMIT(); }

        uint32_t sA = sbase + buf * BUFSZ96;
        uint32_t sB = sA + ABUF;
#pragma unroll
        for (int k16 = 0; k16 < 2; k16++) {
            uint32_t af[4][4], bf[2][4];
#pragma unroll
            for (int mt = 0; mt < 4; mt++)
                ldsm4(af[mt], sA + a_off + mt * 16 * PITCH + k16 * 32);
            ldsm4(bf[0], sB + b_off + k16 * 32);
            ldsm2(bf[1], sB + bodd_off + k16 * 32);
#pragma unroll
            for (int mt = 0; mt < 4; mt++) {
                mma16816(acc[mt][0], af[mt], bf[0][0], bf[0][1]);
                mma16816(acc[mt][1], af[mt], bf[0][2], bf[0][3]);
                mma16816(acc[mt][2], af[mt], bf[1][0], bf[1][1]);
            }
        }
    }

    const int g = lane >> 2, tc = (lane & 3) * 2;
#pragma unroll
    for (int mt = 0; mt < 4; mt++) {
        int row0 = m0 + wm * 64 + mt * 16 + g;
#pragma unroll
        for (int nt = 0; nt < 3; nt++) {
            int col = n0 + wn * 24 + nt * 8 + tc;
            float b0 = bias[col], b1 = bias[col + 1];
            float2 v0 = make_float2(acc[mt][nt][0] + b0, acc[mt][nt][1] + b1);
            float2 v1 = make_float2(acc[mt][nt][2] + b0, acc[mt][nt][3] + b1);
            *(float2*)&C[(size_t)row0 * Dq + col] = v0;
            *(float2*)&C[(size_t)(row0 + 8) * Dq + col] = v1;
        }
    }
}

// ---------------------------------------------------------------------------
// HMMA flash attention (R12 = 488us config, VERBATIM): 128-key tiles,
// 1 CTA/SM, pre-split K/V, double-buffered, single-sync pipeline.
// ---------------------------------------------------------------------------
#define QPB 72
#define VPB 136
#define BUF_HALVES (18432 + 17408)
#define ATTN3_SMEM ((18432 + 2 * BUF_HALVES) * 2)   // 180224 B

__global__ __launch_bounds__(256, 1) void attn_tc_kernel(
    const float* __restrict__ Qg,
    const __nv_bfloat16* __restrict__ KspH, const __nv_bfloat16* __restrict__ KspL,
    const __nv_bfloat16* __restrict__ VtH,  const __nv_bfloat16* __restrict__ VtL,
    __nv_bfloat16* __restrict__ Osp)
{
    extern __shared__ __align__(16) char dsm[];
    __nv_bfloat16* const QH = (__nv_bfloat16*)dsm;
    __nv_bfloat16* const QL = QH + 128 * QPB;
    const uint32_t uQH = smem_u32(QH), uQL = smem_u32(QL);
    const uint32_t uBUF0 = uQH + 18432 * 2;

    const int tid = threadIdx.x, lane = tid & 31, wid = tid >> 5;
    const int g = lane >> 2, t = lane & 3;
    const int q0 = blockIdx.x * 128;
    const int h = blockIdx.y, b = blockIdx.z;
    const int bh = b * Hq + h;
    const size_t base = (size_t)b * Sq * Dq + (size_t)h * HDq;
    const __nv_bfloat16* kH = KspH + (size_t)bh * Sq * HDq;
    const __nv_bfloat16* kL = KspL + (size_t)bh * Sq * HDq;
    const __nv_bfloat16* vH = VtH + (size_t)bh * HDq * Sq;
    const __nv_bfloat16* vL = VtL + (size_t)bh * HDq * Sq;

    const float scl2 = 0.125f * 1.4426950408889634f;

    auto loadKV = [&](int kt, int buf) {
        const int k0 = kt * 128;
        const uint32_t ub = uBUF0 + buf * (BUF_HALVES * 2);
        const uint32_t uKH = ub, uKL = ub + 18432;
        const uint32_t uVH = ub + 36864, uVL = ub + 36864 + 17408;
#pragma unroll
        for (int i = 0; i < 4; i++) {
            int id = tid + 256 * i;
            int r = id >> 3, c = id & 7;
            cpasync16(uKH + r * 144 + c * 16, &kH[(size_t)(k0 + r) * HDq + c * 8]);
            cpasync16(uKL + r * 144 + c * 16, &kL[(size_t)(k0 + r) * HDq + c * 8]);
        }
#pragma unroll
        for (int i = 0; i < 4; i++) {
            int id = tid + 256 * i;
            int r = id >> 4, c = id & 15;
            cpasync16(uVH + r * 272 + c * 16, &vH[(size_t)r * Sq + k0 + c * 8]);
            cpasync16(uVL + r * 272 + c * 16, &vL[(size_t)r * Sq + k0 + c * 8]);
        }
    };

    loadKV(0, 0);
    CP_COMMIT();

#pragma unroll
    for (int i = 0; i < 8; i++) {
        int idx = tid + 256 * i;
        int r = idx >> 4, c = (idx & 15) << 2;
        float4 q = *(const float4*)&Qg[base + (size_t)(q0 + r) * Dq + c];
        q.x *= scl2; q.y *= scl2; q.z *= scl2; q.w *= scl2;
        uint32_t h01 = packbf(q.x, q.y), h23 = packbf(q.z, q.w);
        float2 f0 = unpackbf(h01), f1 = unpackbf(h23);
        *(uint32_t*)&QH[r * QPB + c]     = h01;
        *(uint32_t*)&QH[r * QPB + c + 2] = h23;
        *(uint32_t*)&QL[r * QPB + c]     = packbf(q.x - f0.x, q.y - f0.y);
        *(uint32_t*)&QL[r * QPB + c + 2] = packbf(q.z - f1.x, q.w - f1.y);
    }

    float m0 = -1e30f, m1 = -1e30f, l0 = 0.f, l1 = 0.f;
    float oacc[8][4];
#pragma unroll
    for (int nt = 0; nt < 8; nt++)
#pragma unroll
        for (int i = 0; i < 4; i++) oacc[nt][i] = 0.f;

    const uint32_t a_off  = (uint32_t)((wid * 16 + (lane & 15)) * 144 +
                                       ((lane >> 4) << 4));
    const uint32_t kb_off = (uint32_t)(((lane & 7) + ((lane >> 4) << 3)) * 144 +
                                       (((lane >> 3) & 1) << 4));
    const uint32_t vb_off = (uint32_t)(((lane & 7) + ((lane >> 4) << 3)) * 272 +
                                       (((lane >> 3) & 1) << 4));

    for (int kt = 0; kt < 16; kt++) {
        const int buf = kt & 1;
        CP_WAIT(0);
        __syncthreads();
        if (kt + 1 < 16) { loadKV(kt + 1, buf ^ 1); CP_COMMIT(); }

        const uint32_t ub = uBUF0 + buf * (BUF_HALVES * 2);
        const uint32_t uKH = ub, uKL = ub + 18432;
        const uint32_t uVH = ub + 36864, uVL = ub + 36864 + 17408;

        float sacc[16][4];
#pragma unroll
        for (int nt = 0; nt < 16; nt++)
#pragma unroll
            for (int i = 0; i < 4; i++) sacc[nt][i] = 0.f;

#pragma unroll
        for (int j = 0; j < 4; j++) {
            uint32_t ah[4], al[4];
            ldsm4(ah, uQH + a_off + j * 32);
            ldsm4(al, uQL + a_off + j * 32);
#pragma unroll
            for (int p = 0; p < 8; p++) {
                uint32_t bh4[4], bl4[4];
                ldsm4(bh4, uKH + kb_off + p * (16 * 144) + j * 32);
                ldsm4(bl4, uKL + kb_off + p * (16 * 144) + j * 32);
                mma16816(sacc[2 * p],     ah, bh4[0], bh4[1]);
                mma16816(sacc[2 * p + 1], ah, bh4[2], bh4[3]);
                mma16816(sacc[2 * p],     al, bh4[0], bh4[1]);
                mma16816(sacc[2 * p + 1], al, bh4[2], bh4[3]);
                mma16816(sacc[2 * p],     ah, bl4[0], bl4[1]);
                mma16816(sacc[2 * p + 1], ah, bl4[2], bl4[3]);
            }
        }

        float tmax0 = -1e30f, tmax1 = -1e30f;
#pragma unroll
        for (int nt = 0; nt < 16; nt++) {
            tmax0 = fmaxf(tmax0, fmaxf(sacc[nt][0], sacc[nt][1]));
            tmax1 = fmaxf(tmax1, fmaxf(sacc[nt][2], sacc[nt][3]));
        }
        tmax0 = fmaxf(tmax0, __shfl_xor_sync(0xffffffffu, tmax0, 1));
        tmax0 = fmaxf(tmax0, __shfl_xor_sync(0xffffffffu, tmax0, 2));
        tmax1 = fmaxf(tmax1, __shfl_xor_sync(0xffffffffu, tmax1, 1));
        tmax1 = fmaxf(tmax1, __shfl_xor_sync(0xffffffffu, tmax1, 2));
        float mn0 = fmaxf(m0, tmax0), mn1 = fmaxf(m1, tmax1);
        float al0 = ex2f(m0 - mn0),  al1 = ex2f(m1 - mn1);
        m0 = mn0; m1 = mn1;
        float s0 = 0.f, s1 = 0.f;
#pragma unroll
        for (int nt = 0; nt < 16; nt++) {
            sacc[nt][0] = ex2f(sacc[nt][0] - m0); s0 += sacc[nt][0];
            sacc[nt][1] = ex2f(sacc[nt][1] - m0); s0 += sacc[nt][1];
            sacc[nt][2] = ex2f(sacc[nt][2] - m1); s1 += sacc[nt][2];
            sacc[nt][3] = ex2f(sacc[nt][3] - m1); s1 += sacc[nt][3];
        }
        s0 += __shfl_xor_sync(0xffffffffu, s0, 1);
        s0 += __shfl_xor_sync(0xffffffffu, s0, 2);
        s1 += __shfl_xor_sync(0xffffffffu, s1, 1);
        s1 += __shfl_xor_sync(0xffffffffu, s1, 2);
        l0 = l0 * al0 + s0;
        l1 = l1 * al1 + s1;
#pragma unroll
        for (int nt = 0; nt < 8; nt++) {
            oacc[nt][0] *= al0; oacc[nt][1] *= al0;
            oacc[nt][2] *= al1; oacc[nt][3] *= al1;
        }

#pragma unroll
        for (int j = 0; j < 8; j++) {
            uint32_t Ph[4], Pl[4];
            {
                uint32_t u; float2 f;
                u = packbf(sacc[2*j][0], sacc[2*j][1]); Ph[0] = u;
                f = unpackbf(u);
                Pl[0] = packbf(sacc[2*j][0] - f.x, sacc[2*j][1] - f.y);
                u = packbf(sacc[2*j][2], sacc[2*j][3]); Ph[1] = u;
                f = unpackbf(u);
                Pl[1] = packbf(sacc[2*j][2] - f.x, sacc[2*j][3] - f.y);
                u = packbf(sacc[2*j+1][0], sacc[2*j+1][1]); Ph[2] = u;
                f = unpackbf(u);
                Pl[2] = packbf(sacc[2*j+1][0] - f.x, sacc[2*j+1][1] - f.y);
                u = packbf(sacc[2*j+1][2], sacc[2*j+1][3]); Ph[3] = u;
                f = unpackbf(u);
                Pl[3] = packbf(sacc[2*j+1][2] - f.x, sacc[2*j+1][3] - f.y);
            }
#pragma unroll
            for (int p = 0; p < 4; p++) {
                uint32_t vh4[4], vl4[4];
                ldsm4(vh4, uVH + vb_off + p * (16 * 272) + j * 32);
                ldsm4(vl4, uVL + vb_off + p * (16 * 272) + j * 32);
                mma16816(oacc[2 * p],     Ph, vh4[0], vh4[1]);
                mma16816(oacc[2 * p + 1], Ph, vh4[2], vh4[3]);
                mma16816(oacc[2 * p],     Pl, vh4[0], vh4[1]);
                mma16816(oacc[2 * p + 1], Pl, vh4[2], vh4[3]);
                mma16816(oacc[2 * p],     Ph, vl4[0], vl4[1]);
                mma16816(oacc[2 * p + 1], Ph, vl4[2], vl4[3]);
            }
        }
    }

    const int r0 = b * Sq + q0 + wid * 16 + g, r1 = r0 + 8;
    const float inv0 = 1.f / l0, inv1 = 1.f / l1;
#pragma unroll
    for (int nt = 0; nt < 8; nt++) {
        int col = h * 64 + nt * 8 + t * 2;
        float o00 = oacc[nt][0] * inv0, o01 = oacc[nt][1] * inv0;
        float o10 = oacc[nt][2] * inv1, o11 = oacc[nt][3] * inv1;
        uint32_t hi0 = packbf(o00, o01);
        float2 f0 = unpackbf(hi0);
        uint32_t lo0 = packbf(o00 - f0.x, o01 - f0.y);
        uint32_t hi1 = packbf(o10, o11);
        float2 f1 = unpackbf(hi1);
        uint32_t lo1 = packbf(o10 - f1.x, o11 - f1.y);
        *(uint32_t*)&Osp[(size_t)r0 * K2 + col]       = hi0;
        *(uint32_t*)&Osp[(size_t)r0 * K2 + 768 + col] = lo0;
        *(uint32_t*)&Osp[(size_t)r1 * K2 + col]       = hi1;
        *(uint32_t*)&Osp[(size_t)r1 * K2 + 768 + col] = lo1;
    }
}

// ---------------------------------------------------------------------------
extern "C" void kernel_launch(void* const* d_in, const int* in_sizes, int n_in,
                              void* d_out, int out_size)
{
    const float* query = (const float*)d_in[0];
    const float* key_  = (const float*)d_in[1];
    const float* value = (const float*)d_in[2];
    const float* Wq = (const float*)d_in[3];
    const float* bq = (const float*)d_in[4];
    const float* Wk = (const float*)d_in[5];
    const float* bk = (const float*)d_in[6];
    const float* Wv = (const float*)d_in[7];
    const float* bv = (const float*)d_in[8];
    const float* Wo = (const float*)d_in[9];
    const float* bo = (const float*)d_in[10];
    float* out = (float*)d_out;

    float *pQ, *pK, *pV;
    __nv_bfloat16 *pIsp, *pAsp, *pWsp, *pKH, *pKL, *pVH, *pVL;
    cudaGetSymbolAddress((void**)&pQ, g_Q);
    cudaGetSymbolAddress((void**)&pK, g_K);
    cudaGetSymbolAddress((void**)&pV, g_V);
    cudaGetSymbolAddress((void**)&pIsp, g_Isp);
    cudaGetSymbolAddress((void**)&pAsp, g_Asp);
    cudaGetSymbolAddress((void**)&pWsp, g_Wsp);
    cudaGetSymbolAddress((void**)&pKH, g_KspH);
    cudaGetSymbolAddress((void**)&pKL, g_KspL);
    cudaGetSymbolAddress((void**)&pVH, g_VtH);
    cudaGetSymbolAddress((void**)&pVL, g_VtL);

    cudaFuncSetAttribute(attn_tc_kernel,
                         cudaFuncAttributeMaxDynamicSharedMemorySize,
                         ATTN3_SMEM);

    // 1) split inputs -> bf16 hi|lo
    SplitInArgs si;
    si.src[0] = query; si.src[1] = key_; si.src[2] = value;
    si.dst[0] = pIsp;  si.dst[1] = pIsp + (size_t)Mrows * K2;
    si.dst[2] = pIsp + 2 * (size_t)Mrows * K2;
    split_in_kernel<<<dim3(3072, 1, 3), 256>>>(si);

    // 2) split + transpose weights
    SplitWArgs sw;
    sw.W[0] = Wq; sw.W[1] = Wk; sw.W[2] = Wv; sw.W[3] = Wo;
    for (int i = 0; i < 4; i++) sw.Wt[i] = pWsp + (size_t)i * Dq * K2;
    split_w_kernel<<<dim3(24, 24, 4), dim3(32, 8)>>>(sw);

    // 3) QKV projections (R12 GEMM, verbatim)
    TcGemmArgs qkv;
    for (int i = 0; i < 3; i++) {
        qkv.A[i]  = pIsp + (size_t)i * Mrows * K2;
        qkv.Wt[i] = pWsp + (size_t)i * Dq * K2;
    }
    qkv.bias[0] = bq; qkv.bias[1] = bk; qkv.bias[2] = bv;
    qkv.C[0] = pQ;    qkv.C[1] = pK;    qkv.C[2] = pV;
    gemm_tc_kernel<<<dim3(Mrows / 128, Dq / 128, 3), 256>>>(qkv);

    // 4) pre-split K + transpose-split V (R12 prep kernels)
    split_k_kernel<<<3072, 256>>>(pK, pKH, pKL);
    transpose_v_kernel<<<dim3(Sq / 32, HDq / 32, BH), dim3(32, 8)>>>(pV, pVH, pVL);

    // 5) attention (R12 config, verbatim)
    dim3 ga(Sq / 128, Hq, Bq);
    attn_tc_kernel<<<ga, 256, ATTN3_SMEM>>>(pQ, pKH, pKL, pVH, pVL, pAsp);

    // 6) output projection: dedicated 128x96-tile kernel (256 CTAs, 86% fill)
    gemm_tc96_kernel<<<dim3(Mrows / 128, Dq / 96), 256>>>(
        pAsp, pWsp + 3 * (size_t)Dq * K2, bo, out);
}